// round 15
// baseline (speedup 1.0000x reference)
#include <cuda_runtime.h>
#include <cuda_fp16.h>
#include <cstdint>
#include <cstddef>

#define CDIM 224
#define SCALE_Q 0.18898223650461363f
#define STAGE_H 9600              // 128*40 (A) + 112*40 (B) halves
#define NSTAGE 3
#define GEMM_SMEM_BYTES (NSTAGE * STAGE_H * 2)

__device__ __half g_QH[29360128];
__device__ __half g_KH[29360128];
__device__ __half g_VH[29360128];
__device__ __half g_AttnH[29360128];
__device__ __half g_X[29360128];
__device__ __half g_WqT[50176];
__device__ __half g_WkvT[100352];
__device__ __half g_WoutT[50176];

__device__ __forceinline__ void cp16h(__half* smem_dst, const __half* gsrc) {
    unsigned s = (unsigned)__cvta_generic_to_shared(smem_dst);
    asm volatile("cp.async.cg.shared.global [%0], [%1], 16;" :: "r"(s), "l"(gsrc) : "memory");
}
__device__ __forceinline__ void ldsm4(unsigned& r0, unsigned& r1, unsigned& r2, unsigned& r3,
                                      const __half* p) {
    uint32_t a = (uint32_t)__cvta_generic_to_shared(p);
    asm volatile("ldmatrix.sync.aligned.m8n8.x4.shared.b16 {%0,%1,%2,%3}, [%4];"
                 : "=r"(r0), "=r"(r1), "=r"(r2), "=r"(r3) : "r"(a));
}
__device__ __forceinline__ void ldsm2(unsigned& r0, unsigned& r1, const __half* p) {
    uint32_t a = (uint32_t)__cvta_generic_to_shared(p);
    asm volatile("ldmatrix.sync.aligned.m8n8.x2.shared.b16 {%0,%1}, [%2];"
                 : "=r"(r0), "=r"(r1) : "r"(a));
}
#define MMA_F16(acc, a0,a1,a2,a3, b0,b1) \
    asm volatile("mma.sync.aligned.m16n8k16.row.col.f32.f16.f16.f32 " \
        "{%0,%1,%2,%3}, {%4,%5,%6,%7}, {%8,%9}, {%0,%1,%2,%3};\n" \
        : "+f"(acc[0]), "+f"(acc[1]), "+f"(acc[2]), "+f"(acc[3]) \
        : "r"(a0), "r"(a1), "r"(a2), "r"(a3), "r"(b0), "r"(b1))

// ---------------- prepasses ----------------
__global__ __launch_bounds__(256) void conv_x(
    const float* __restrict__ src, __half* __restrict__ dst, int n4)
{
    int i = blockIdx.x * blockDim.x + threadIdx.x;
    if (i < n4) {
        float4 f = reinterpret_cast<const float4*>(src)[i];
        half2 h0 = __floats2half2_rn(f.x, f.y);
        half2 h1 = __floats2half2_rn(f.z, f.w);
        *reinterpret_cast<uint2*>(dst + 4 * (size_t)i) =
            make_uint2(*reinterpret_cast<unsigned*>(&h0), *reinterpret_cast<unsigned*>(&h1));
    }
}
// fused transpose+convert for all three weight matrices:
// blockIdx.x in [0,28): [0,7)->Wq, [7,21)->Wkv, [21,28)->Wout; blockIdx.y = k-block
__global__ __launch_bounds__(1024) void transp_conv_all(
    const float* __restrict__ Wq, const float* __restrict__ Wkv, const float* __restrict__ Wout,
    __half* __restrict__ WqT, __half* __restrict__ WkvT, __half* __restrict__ WoutT)
{
    __shared__ float t[32][33];
    int bx = blockIdx.x;
    const float* W; __half* WT; int N, nb;
    if (bx < 7)       { W = Wq;   WT = WqT;   N = 224; nb = bx; }
    else if (bx < 21) { W = Wkv;  WT = WkvT;  N = 448; nb = bx - 7; }
    else              { W = Wout; WT = WoutT; N = 224; nb = bx - 21; }
    int n0 = nb * 32, k0 = blockIdx.y * 32;
    t[threadIdx.y][threadIdx.x] = W[(size_t)(k0 + threadIdx.y) * N + n0 + threadIdx.x];
    __syncthreads();
    WT[(size_t)(n0 + threadIdx.y) * 224 + k0 + threadIdx.x] =
        __float2half_rn(t[threadIdx.x][threadIdx.y]);
}

// ---------------- fp16 3-stage pipelined GEMM + ldmatrix: BM=128 BN=112 BK=32 ----------------
__device__ __forceinline__ void gemm_fp16(
    const __half* __restrict__ A, const __half* __restrict__ BT,
    __half* smem, float (&acc)[2][7][4])
{
    const int tid = threadIdx.x;
    const int wid = tid >> 5, lane = tid & 31;
    const int wm = wid >> 1, wn = wid & 1;

    const int laA  = lane & 15;
    const int kaA  = (lane >> 4) * 8;
    const int lbB  = lane & 7;
    const int kbB  = ((lane >> 3) & 1) * 8;
    const int nsB  = ((lane >> 4) & 1) * 8;

    auto issue = [&](int kt, int stage) {
        __half* sA = smem + stage * STAGE_H;
        __half* sB = sA + 5120;
        #pragma unroll
        for (int p = 0; p < 2; p++) {
            int q = tid + p * 256;
            int r = q >> 2, c8 = (q & 3) * 8;
            cp16h(sA + r * 40 + c8, A + (size_t)r * CDIM + kt + c8);
        }
        #pragma unroll
        for (int p = 0; p < 2; p++) {
            int q = tid + p * 256;
            if (q < 448) {
                int n = q >> 2, c8 = (q & 3) * 8;
                cp16h(sB + n * 40 + c8, BT + (size_t)n * CDIM + kt + c8);
            }
        }
        asm volatile("cp.async.commit_group;" ::: "memory");
    };

    issue(0, 0);
    issue(32, 1);
    #pragma unroll
    for (int it = 0; it < 7; it++) {
        if (it == 6) asm volatile("cp.async.wait_group 0;" ::: "memory");
        else         asm volatile("cp.async.wait_group 1;" ::: "memory");
        __syncthreads();
        __half* sA = smem + (it % NSTAGE) * STAGE_H;
        __half* sB = sA + 5120;
        #pragma unroll
        for (int ks = 0; ks < 2; ks++) {
            const int kb = ks * 16;
            unsigned af[2][4];
            #pragma unroll
            for (int mt = 0; mt < 2; mt++)
                ldsm4(af[mt][0], af[mt][1], af[mt][2], af[mt][3],
                      sA + (wm * 32 + mt * 16 + laA) * 40 + kb + kaA);
            unsigned bf[7][2];
            #pragma unroll
            for (int ntp = 0; ntp < 3; ntp++)
                ldsm4(bf[2 * ntp][0], bf[2 * ntp][1], bf[2 * ntp + 1][0], bf[2 * ntp + 1][1],
                      sB + (wn * 56 + ntp * 16 + nsB + lbB) * 40 + kb + kbB);
            ldsm2(bf[6][0], bf[6][1], sB + (wn * 56 + 48 + lbB) * 40 + kb + kbB);
            #pragma unroll
            for (int mt = 0; mt < 2; mt++)
                #pragma unroll
                for (int nt = 0; nt < 7; nt++)
                    MMA_F16(acc[mt][nt], af[mt][0], af[mt][1], af[mt][2], af[mt][3],
                            bf[nt][0], bf[nt][1]);
        }
        if (it + 2 < 7) issue((it + 2) * 32, (it + 2) % NSTAGE);
    }
}

// ---------------- kernel 1: QKV + window-partition permute + q*SCALE (fp16 out) ----------------
__global__ __launch_bounds__(256, 3) void qkv_kernel()
{
    extern __shared__ __half smem[];
    float acc[2][7][4] = {};
    const int ctan = blockIdx.x, ctam = blockIdx.y;

    const __half* BT;
    if (ctan < 2) BT = g_WqT  + (size_t)(ctan * 112) * CDIM;
    else          BT = g_WkvT + (size_t)((ctan - 2) * 112) * CDIM;

    gemm_fp16(g_X + (size_t)ctam * 128 * CDIM, BT, smem, acc);

    __half* Dst = (ctan < 2) ? g_QH : (ctan < 4 ? g_KH : g_VH);
    const float scale = (ctan < 2) ? SCALE_Q : 1.0f;
    const int tid = threadIdx.x, wid = tid >> 5, lane = tid & 31;
    const int g = lane >> 2, tig = lane & 3, wm = wid >> 1, wn = wid & 1;
    const int joff = (ctan & 1) * 112 + wn * 56 + tig * 2;

    #pragma unroll
    for (int mt = 0; mt < 2; mt++)
        #pragma unroll
        for (int rh = 0; rh < 2; rh++) {
            int r = wm * 32 + mt * 16 + rh * 8 + g;
            int t = ctam * 128 + r;
            int b = t >> 10, hr = (t >> 5) & 31, wc = t & 31;
            int n = ((hr >> 3) << 2) + (wc >> 3);
            int i = ((hr & 7) << 3) + (wc & 7);
            __half* base = Dst + ((size_t)((b * 16 + n) * 64 + i)) * CDIM + joff;
            #pragma unroll
            for (int nt = 0; nt < 7; nt++)
                *reinterpret_cast<half2*>(base + nt * 8) = __floats2half2_rn(
                    acc[mt][nt][rh * 2 + 0] * scale, acc[mt][nt][rh * 2 + 1] * scale);
        }
}

// ---------------- kernel 2: local window attention, fp16 tensor cores ----------------
__global__ __launch_bounds__(128) void local_attn(const float* __restrict__ pe1)
{
    __shared__ __half sQ[64 * 40];
    __shared__ __half sK[64 * 40];
    __shared__ __half sVT[32 * 72];
    __shared__ __half sP[64 * 72];

    const int tid = threadIdx.x;
    const int wid = tid >> 5, lane = tid & 31;
    const int g = lane >> 2, tig = lane & 3;
    const int m0 = wid * 16;
    const size_t rowbase = (size_t)blockIdx.x * 64 * CDIM;
    const __half hz = __float2half(0.f);

    for (int i = tid; i < 256; i += 128) {
        int r = i >> 2, c = 28 + (i & 3);
        sQ[r * 40 + c] = hz; sK[r * 40 + c] = hz;
    }
    for (int i = tid; i < 288; i += 128) sVT[28 * 72 + i] = hz;
    __syncthreads();

    for (int h = 0; h < 4; h++) {
        const int ch0 = h * 28;
        #pragma unroll
        for (int p = 0; p < 4; p++) {
            int idx = tid + p * 128;
            if (idx < 448) {
                int rr = idx / 7, c4 = (idx % 7) << 2;
                size_t ga = rowbase + (size_t)rr * CDIM + ch0 + c4;
                *reinterpret_cast<uint2*>(sQ + rr * 40 + c4) =
                    *reinterpret_cast<const uint2*>(g_QH + ga);
                *reinterpret_cast<uint2*>(sK + rr * 40 + c4) =
                    *reinterpret_cast<const uint2*>(g_KH + ga);
                uint2 v = *reinterpret_cast<const uint2*>(g_VH + ga);
                __half2 v01 = *reinterpret_cast<__half2*>(&v.x);
                __half2 v23 = *reinterpret_cast<__half2*>(&v.y);
                sVT[(c4 + 0) * 72 + rr] = __low2half(v01);
                sVT[(c4 + 1) * 72 + rr] = __high2half(v01);
                sVT[(c4 + 2) * 72 + rr] = __low2half(v23);
                sVT[(c4 + 3) * 72 + rr] = __high2half(v23);
            }
        }
        __syncthreads();

        float accS[8][4];
        #pragma unroll
        for (int nt = 0; nt < 8; nt++)
            #pragma unroll
            for (int e = 0; e < 4; e++) accS[nt][e] = 0.f;
        #pragma unroll
        for (int ks = 0; ks < 2; ks++) {
            const int kb = ks * 16;
            unsigned a0 = *reinterpret_cast<const unsigned*>(sQ + (m0 + g) * 40 + kb + 2 * tig);
            unsigned a1 = *reinterpret_cast<const unsigned*>(sQ + (m0 + 8 + g) * 40 + kb + 2 * tig);
            unsigned a2 = *reinterpret_cast<const unsigned*>(sQ + (m0 + g) * 40 + kb + 8 + 2 * tig);
            unsigned a3 = *reinterpret_cast<const unsigned*>(sQ + (m0 + 8 + g) * 40 + kb + 8 + 2 * tig);
            #pragma unroll
            for (int nt = 0; nt < 8; nt++) {
                unsigned b0 = *reinterpret_cast<const unsigned*>(sK + (nt * 8 + g) * 40 + kb + 2 * tig);
                unsigned b1 = *reinterpret_cast<const unsigned*>(sK + (nt * 8 + g) * 40 + kb + 8 + 2 * tig);
                MMA_F16(accS[nt], a0, a1, a2, a3, b0, b1);
            }
        }

        const float* pe = pe1 + (size_t)h * 4096;
        #pragma unroll
        for (int nt = 0; nt < 8; nt++) {
            float2 p0 = *reinterpret_cast<const float2*>(pe + (m0 + g) * 64 + nt * 8 + 2 * tig);
            float2 p1 = *reinterpret_cast<const float2*>(pe + (m0 + 8 + g) * 64 + nt * 8 + 2 * tig);
            accS[nt][0] += p0.x; accS[nt][1] += p0.y;
            accS[nt][2] += p1.x; accS[nt][3] += p1.y;
        }
        float m0v = -1e30f, m1v = -1e30f;
        #pragma unroll
        for (int nt = 0; nt < 8; nt++) {
            m0v = fmaxf(m0v, fmaxf(accS[nt][0], accS[nt][1]));
            m1v = fmaxf(m1v, fmaxf(accS[nt][2], accS[nt][3]));
        }
        m0v = fmaxf(m0v, __shfl_xor_sync(0xffffffffu, m0v, 1));
        m0v = fmaxf(m0v, __shfl_xor_sync(0xffffffffu, m0v, 2));
        m1v = fmaxf(m1v, __shfl_xor_sync(0xffffffffu, m1v, 1));
        m1v = fmaxf(m1v, __shfl_xor_sync(0xffffffffu, m1v, 2));
        float s0 = 0.f, s1 = 0.f;
        #pragma unroll
        for (int nt = 0; nt < 8; nt++) {
            accS[nt][0] = __expf(accS[nt][0] - m0v); s0 += accS[nt][0];
            accS[nt][1] = __expf(accS[nt][1] - m0v); s0 += accS[nt][1];
            accS[nt][2] = __expf(accS[nt][2] - m1v); s1 += accS[nt][2];
            accS[nt][3] = __expf(accS[nt][3] - m1v); s1 += accS[nt][3];
        }
        s0 += __shfl_xor_sync(0xffffffffu, s0, 1);
        s0 += __shfl_xor_sync(0xffffffffu, s0, 2);
        s1 += __shfl_xor_sync(0xffffffffu, s1, 1);
        s1 += __shfl_xor_sync(0xffffffffu, s1, 2);
        const float i0 = 1.f / s0, i1 = 1.f / s1;
        #pragma unroll
        for (int nt = 0; nt < 8; nt++) {
            *reinterpret_cast<half2*>(sP + (m0 + g) * 72 + nt * 8 + 2 * tig) =
                __floats2half2_rn(accS[nt][0] * i0, accS[nt][1] * i0);
            *reinterpret_cast<half2*>(sP + (m0 + 8 + g) * 72 + nt * 8 + 2 * tig) =
                __floats2half2_rn(accS[nt][2] * i1, accS[nt][3] * i1);
        }
        __syncwarp();

        float accO[4][4];
        #pragma unroll
        for (int nt = 0; nt < 4; nt++)
            #pragma unroll
            for (int e = 0; e < 4; e++) accO[nt][e] = 0.f;
        #pragma unroll
        for (int ks = 0; ks < 4; ks++) {
            const int kb = ks * 16;
            unsigned a0 = *reinterpret_cast<const unsigned*>(sP + (m0 + g) * 72 + kb + 2 * tig);
            unsigned a1 = *reinterpret_cast<const unsigned*>(sP + (m0 + 8 + g) * 72 + kb + 2 * tig);
            unsigned a2 = *reinterpret_cast<const unsigned*>(sP + (m0 + g) * 72 + kb + 8 + 2 * tig);
            unsigned a3 = *reinterpret_cast<const unsigned*>(sP + (m0 + 8 + g) * 72 + kb + 8 + 2 * tig);
            #pragma unroll
            for (int nt = 0; nt < 4; nt++) {
                unsigned b0 = *reinterpret_cast<const unsigned*>(sVT + (nt * 8 + g) * 72 + kb + 2 * tig);
                unsigned b1 = *reinterpret_cast<const unsigned*>(sVT + (nt * 8 + g) * 72 + kb + 8 + 2 * tig);
                MMA_F16(accO[nt], a0, a1, a2, a3, b0, b1);
            }
        }
        __half* row0 = g_AttnH + rowbase + (size_t)(m0 + g) * CDIM;
        __half* row1 = g_AttnH + rowbase + (size_t)(m0 + 8 + g) * CDIM;
        #pragma unroll
        for (int nt = 0; nt < 4; nt++) {
            int col = nt * 8 + 2 * tig;
            if (col < 28) {
                *reinterpret_cast<half2*>(row0 + ch0 + col) =
                    __floats2half2_rn(accO[nt][0], accO[nt][1]);
                *reinterpret_cast<half2*>(row1 + ch0 + col) =
                    __floats2half2_rn(accO[nt][2], accO[nt][3]);
            }
        }
        __syncthreads();
    }
}

// ---------------- kernel 3: global attention (channels 112..223) ----------------
__global__ __launch_bounds__(128) void global_attn(const float* __restrict__ pe2)
{
    __shared__ float qs[16 * 116];
    __shared__ float kTs[112 * 20];
    __shared__ float vs[16 * 116];
    __shared__ float ps[4 * 16 * 17];

    const int tid = threadIdx.x;
    const int b = blockIdx.x >> 6, ipos = blockIdx.x & 63;
    const size_t base0 = ((size_t)(b * 16) * 64 + ipos) * CDIM + 112;

    #pragma unroll
    for (int p = 0; p < 4; p++) {
        int idx = tid + p * 128;
        if (idx < 448) {
            int n = idx / 28, c4 = (idx % 28) << 2;
            size_t ga = base0 + (size_t)n * (64 * CDIM) + c4;
            uint2 qv = *reinterpret_cast<const uint2*>(g_QH + ga);
            uint2 vv = *reinterpret_cast<const uint2*>(g_VH + ga);
            uint2 kv = *reinterpret_cast<const uint2*>(g_KH + ga);
            float2 q01 = __half22float2(*reinterpret_cast<__half2*>(&qv.x));
            float2 q23 = __half22float2(*reinterpret_cast<__half2*>(&qv.y));
            float2 v01 = __half22float2(*reinterpret_cast<__half2*>(&vv.x));
            float2 v23 = __half22float2(*reinterpret_cast<__half2*>(&vv.y));
            float2 k01 = __half22float2(*reinterpret_cast<__half2*>(&kv.x));
            float2 k23 = __half22float2(*reinterpret_cast<__half2*>(&kv.y));
            qs[n * 116 + c4 + 0] = q01.x; qs[n * 116 + c4 + 1] = q01.y;
            qs[n * 116 + c4 + 2] = q23.x; qs[n * 116 + c4 + 3] = q23.y;
            vs[n * 116 + c4 + 0] = v01.x; vs[n * 116 + c4 + 1] = v01.y;
            vs[n * 116 + c4 + 2] = v23.x; vs[n * 116 + c4 + 3] = v23.y;
            kTs[(c4 + 0) * 20 + n] = k01.x; kTs[(c4 + 1) * 20 + n] = k01.y;
            kTs[(c4 + 2) * 20 + n] = k23.x; kTs[(c4 + 3) * 20 + n] = k23.y;
        }
    }
    __syncthreads();

    const int h = tid >> 5, lane = tid & 31;
    const int r = lane >> 1, cb = (lane & 1) << 3;

    float qreg[28];
    #pragma unroll
    for (int u = 0; u < 7; u++) {
        float4 f = *reinterpret_cast<float4*>(qs + r * 116 + h * 28 + 4 * u);
        qreg[4 * u] = f.x; qreg[4 * u + 1] = f.y; qreg[4 * u + 2] = f.z; qreg[4 * u + 3] = f.w;
    }
    float s[8];
    #pragma unroll
    for (int j = 0; j < 8; j++) s[j] = 0.f;
    #pragma unroll
    for (int d = 0; d < 28; d++)
        #pragma unroll
        for (int j = 0; j < 8; j++) s[j] += qreg[d] * kTs[(h * 28 + d) * 20 + cb + j];

    const float* pr = pe2 + (size_t)h * 256 + r * 16 + cb;
    #pragma unroll
    for (int j = 0; j < 8; j++) s[j] += pr[j];
    float m = s[0];
    #pragma unroll
    for (int j = 1; j < 8; j++) m = fmaxf(m, s[j]);
    m = fmaxf(m, __shfl_xor_sync(0xffffffffu, m, 1));
    float sum = 0.f;
    #pragma unroll
    for (int j = 0; j < 8; j++) { s[j] = __expf(s[j] - m); sum += s[j]; }
    sum += __shfl_xor_sync(0xffffffffu, sum, 1);
    const float inv = 1.f / sum;
    #pragma unroll
    for (int j = 0; j < 8; j++) ps[h * 272 + r * 17 + cb + j] = s[j] * inv;
    __syncwarp();

    const int chb = (lane & 1) * 14;
    float accO[14];
    #pragma unroll
    for (int c = 0; c < 14; c++) accO[c] = 0.f;
    #pragma unroll
    for (int j = 0; j < 16; j++) {
        float p = ps[h * 272 + r * 17 + j];
        #pragma unroll
        for (int c = 0; c < 14; c++) accO[c] += p * vs[j * 116 + h * 28 + chb + c];
    }
    __half* od = g_AttnH + ((size_t)((b * 16 + r) * 64 + ipos)) * CDIM + 112 + h * 28 + chb;
    #pragma unroll
    for (int c = 0; c < 14; c++) od[c] = __float2half_rn(accO[c]);
}

// ---------------- kernel 4: out-proj + bias + window-reverse ----------------
__global__ __launch_bounds__(256, 3) void proj_kernel(
    const float* __restrict__ bout, float* __restrict__ out)
{
    extern __shared__ __half smem[];
    float acc[2][7][4] = {};
    const int ctan = blockIdx.x, ctam = blockIdx.y;

    gemm_fp16(g_AttnH + (size_t)ctam * 128 * CDIM,
              g_WoutT + (size_t)(ctan * 112) * CDIM, smem, acc);

    const int tid = threadIdx.x, wid = tid >> 5, lane = tid & 31;
    const int g = lane >> 2, tig = lane & 3, wm = wid >> 1, wn = wid & 1;
    const int joff = ctan * 112 + wn * 56 + tig * 2;

    #pragma unroll
    for (int mt = 0; mt < 2; mt++)
        #pragma unroll
        for (int rh = 0; rh < 2; rh++) {
            int r = wm * 32 + mt * 16 + rh * 8 + g;
            int t = ctam * 128 + r;
            int b = t >> 10, n = (t >> 6) & 15, i = t & 63;
            int hr = (n >> 2) * 8 + (i >> 3), wc = (n & 3) * 8 + (i & 7);
            float* base = out + ((size_t)((b * 32 + hr) * 32 + wc)) * CDIM + joff;
            #pragma unroll
            for (int nt = 0; nt < 7; nt++) {
                float2 bo = *reinterpret_cast<const float2*>(bout + joff + nt * 8);
                *reinterpret_cast<float2*>(base + nt * 8) =
                    make_float2(acc[mt][nt][rh * 2 + 0] + bo.x, acc[mt][nt][rh * 2 + 1] + bo.y);
            }
        }
}

extern "C" void kernel_launch(void* const* d_in, const int* in_sizes, int n_in,
                              void* d_out, int out_size) {
    const float* x    = (const float*)d_in[0];
    const float* Wq   = (const float*)d_in[1];
    const float* Wkv  = (const float*)d_in[2];
    const float* Wout = (const float*)d_in[3];
    const float* bout = (const float*)d_in[4];
    const float* pe1  = (const float*)d_in[5];
    const float* pe2  = (const float*)d_in[6];
    float* out = (float*)d_out;

    cudaFuncSetAttribute(qkv_kernel,  cudaFuncAttributeMaxDynamicSharedMemorySize, GEMM_SMEM_BYTES);
    cudaFuncSetAttribute(proj_kernel, cudaFuncAttributeMaxDynamicSharedMemorySize, GEMM_SMEM_BYTES);

    __half* gX;     cudaGetSymbolAddress((void**)&gX,     g_X);
    __half* gWqT;   cudaGetSymbolAddress((void**)&gWqT,   g_WqT);
    __half* gWkvT;  cudaGetSymbolAddress((void**)&gWkvT,  g_WkvT);
    __half* gWoutT; cudaGetSymbolAddress((void**)&gWoutT, g_WoutT);

    conv_x<<<28672, 256>>>(x, gX, 29360128 / 4);
    transp_conv_all<<<dim3(28, 7), dim3(32, 32)>>>(Wq, Wkv, Wout, gWqT, gWkvT, gWoutT);

    qkv_kernel<<<dim3(6, 1024), 256, GEMM_SMEM_BYTES>>>();
    local_attn<<<2048, 128>>>(pe1);
    global_attn<<<8192, 128>>>(pe2);
    proj_kernel<<<dim3(2, 1024), 256, GEMM_SMEM_BYTES>>>(bout, out);
}

// round 16
// speedup vs baseline: 1.0778x; 1.0778x over previous
#include <cuda_runtime.h>
#include <cuda_fp16.h>
#include <cstdint>
#include <cstddef>

#define CDIM 224
#define SCALE_Q 0.18898223650461363f
#define STAGE_H 9600              // 128*40 (A) + 112*40 (B) halves
#define NSTAGE 3
#define GEMM_SMEM_BYTES (NSTAGE * STAGE_H * 2)

__device__ __half g_QH[29360128];
__device__ __half g_KH[29360128];
__device__ __half g_VH[29360128];
__device__ __half g_AttnH[29360128];
__device__ __half g_X[29360128];
__device__ __half g_WqT[50176];
__device__ __half g_WkvT[100352];
__device__ __half g_WoutT[50176];

__device__ __forceinline__ void cp16h(__half* smem_dst, const __half* gsrc) {
    unsigned s = (unsigned)__cvta_generic_to_shared(smem_dst);
    asm volatile("cp.async.cg.shared.global [%0], [%1], 16;" :: "r"(s), "l"(gsrc) : "memory");
}
__device__ __forceinline__ void ldsm4(unsigned& r0, unsigned& r1, unsigned& r2, unsigned& r3,
                                      const __half* p) {
    uint32_t a = (uint32_t)__cvta_generic_to_shared(p);
    asm volatile("ldmatrix.sync.aligned.m8n8.x4.shared.b16 {%0,%1,%2,%3}, [%4];"
                 : "=r"(r0), "=r"(r1), "=r"(r2), "=r"(r3) : "r"(a));
}
__device__ __forceinline__ void ldsm2(unsigned& r0, unsigned& r1, const __half* p) {
    uint32_t a = (uint32_t)__cvta_generic_to_shared(p);
    asm volatile("ldmatrix.sync.aligned.m8n8.x2.shared.b16 {%0,%1}, [%2];"
                 : "=r"(r0), "=r"(r1) : "r"(a));
}
#define MMA_F16(acc, a0,a1,a2,a3, b0,b1) \
    asm volatile("mma.sync.aligned.m16n8k16.row.col.f32.f16.f16.f32 " \
        "{%0,%1,%2,%3}, {%4,%5,%6,%7}, {%8,%9}, {%0,%1,%2,%3};\n" \
        : "+f"(acc[0]), "+f"(acc[1]), "+f"(acc[2]), "+f"(acc[3]) \
        : "r"(a0), "r"(a1), "r"(a2), "r"(a3), "r"(b0), "r"(b1))

// ---------------- prepasses ----------------
__global__ __launch_bounds__(256) void conv_x(
    const float* __restrict__ src, __half* __restrict__ dst, int n4)
{
    int i = blockIdx.x * blockDim.x + threadIdx.x;
    if (i < n4) {
        float4 f = reinterpret_cast<const float4*>(src)[i];
        half2 h0 = __floats2half2_rn(f.x, f.y);
        half2 h1 = __floats2half2_rn(f.z, f.w);
        *reinterpret_cast<uint2*>(dst + 4 * (size_t)i) =
            make_uint2(*reinterpret_cast<unsigned*>(&h0), *reinterpret_cast<unsigned*>(&h1));
    }
}
__global__ __launch_bounds__(1024) void transp_conv_all(
    const float* __restrict__ Wq, const float* __restrict__ Wkv, const float* __restrict__ Wout,
    __half* __restrict__ WqT, __half* __restrict__ WkvT, __half* __restrict__ WoutT)
{
    __shared__ float t[32][33];
    int bx = blockIdx.x;
    const float* W; __half* WT; int N, nb;
    if (bx < 7)       { W = Wq;   WT = WqT;   N = 224; nb = bx; }
    else if (bx < 21) { W = Wkv;  WT = WkvT;  N = 448; nb = bx - 7; }
    else              { W = Wout; WT = WoutT; N = 224; nb = bx - 21; }
    int n0 = nb * 32, k0 = blockIdx.y * 32;
    t[threadIdx.y][threadIdx.x] = W[(size_t)(k0 + threadIdx.y) * N + n0 + threadIdx.x];
    __syncthreads();
    WT[(size_t)(n0 + threadIdx.y) * 224 + k0 + threadIdx.x] =
        __float2half_rn(t[threadIdx.x][threadIdx.y]);
}

// ---------------- fp16 3-stage pipelined GEMM + ldmatrix: BM=128 BN=112 BK=32 ----------------
__device__ __forceinline__ void gemm_fp16(
    const __half* __restrict__ A, const __half* __restrict__ BT,
    __half* smem, float (&acc)[2][7][4])
{
    const int tid = threadIdx.x;
    const int wid = tid >> 5, lane = tid & 31;
    const int wm = wid >> 1, wn = wid & 1;

    const int laA  = lane & 15;
    const int kaA  = (lane >> 4) * 8;
    const int lbB  = lane & 7;
    const int kbB  = ((lane >> 3) & 1) * 8;
    const int nsB  = ((lane >> 4) & 1) * 8;

    auto issue = [&](int kt, int stage) {
        __half* sA = smem + stage * STAGE_H;
        __half* sB = sA + 5120;
        #pragma unroll
        for (int p = 0; p < 2; p++) {
            int q = tid + p * 256;
            int r = q >> 2, c8 = (q & 3) * 8;
            cp16h(sA + r * 40 + c8, A + (size_t)r * CDIM + kt + c8);
        }
        #pragma unroll
        for (int p = 0; p < 2; p++) {
            int q = tid + p * 256;
            if (q < 448) {
                int n = q >> 2, c8 = (q & 3) * 8;
                cp16h(sB + n * 40 + c8, BT + (size_t)n * CDIM + kt + c8);
            }
        }
        asm volatile("cp.async.commit_group;" ::: "memory");
    };

    issue(0, 0);
    issue(32, 1);
    #pragma unroll
    for (int it = 0; it < 7; it++) {
        if (it == 6) asm volatile("cp.async.wait_group 0;" ::: "memory");
        else         asm volatile("cp.async.wait_group 1;" ::: "memory");
        __syncthreads();
        __half* sA = smem + (it % NSTAGE) * STAGE_H;
        __half* sB = sA + 5120;
        #pragma unroll
        for (int ks = 0; ks < 2; ks++) {
            const int kb = ks * 16;
            unsigned af[2][4];
            #pragma unroll
            for (int mt = 0; mt < 2; mt++)
                ldsm4(af[mt][0], af[mt][1], af[mt][2], af[mt][3],
                      sA + (wm * 32 + mt * 16 + laA) * 40 + kb + kaA);
            unsigned bf[7][2];
            #pragma unroll
            for (int ntp = 0; ntp < 3; ntp++)
                ldsm4(bf[2 * ntp][0], bf[2 * ntp][1], bf[2 * ntp + 1][0], bf[2 * ntp + 1][1],
                      sB + (wn * 56 + ntp * 16 + nsB + lbB) * 40 + kb + kbB);
            ldsm2(bf[6][0], bf[6][1], sB + (wn * 56 + 48 + lbB) * 40 + kb + kbB);
            #pragma unroll
            for (int mt = 0; mt < 2; mt++)
                #pragma unroll
                for (int nt = 0; nt < 7; nt++)
                    MMA_F16(acc[mt][nt], af[mt][0], af[mt][1], af[mt][2], af[mt][3],
                            bf[nt][0], bf[nt][1]);
        }
        if (it + 2 < 7) issue((it + 2) * 32, (it + 2) % NSTAGE);
    }
}

// ---------------- kernel 1: QKV + window-partition permute + q*SCALE (fp16 out) ----------------
__global__ __launch_bounds__(256, 2) void qkv_kernel()
{
    extern __shared__ __half smem[];
    float acc[2][7][4] = {};
    const int ctan = blockIdx.x, ctam = blockIdx.y;

    const __half* BT;
    if (ctan < 2) BT = g_WqT  + (size_t)(ctan * 112) * CDIM;
    else          BT = g_WkvT + (size_t)((ctan - 2) * 112) * CDIM;

    gemm_fp16(g_X + (size_t)ctam * 128 * CDIM, BT, smem, acc);

    __half* Dst = (ctan < 2) ? g_QH : (ctan < 4 ? g_KH : g_VH);
    const float scale = (ctan < 2) ? SCALE_Q : 1.0f;
    const int tid = threadIdx.x, wid = tid >> 5, lane = tid & 31;
    const int g = lane >> 2, tig = lane & 3, wm = wid >> 1, wn = wid & 1;
    const int joff = (ctan & 1) * 112 + wn * 56 + tig * 2;

    #pragma unroll
    for (int mt = 0; mt < 2; mt++)
        #pragma unroll
        for (int rh = 0; rh < 2; rh++) {
            int r = wm * 32 + mt * 16 + rh * 8 + g;
            int t = ctam * 128 + r;
            int b = t >> 10, hr = (t >> 5) & 31, wc = t & 31;
            int n = ((hr >> 3) << 2) + (wc >> 3);
            int i = ((hr & 7) << 3) + (wc & 7);
            __half* base = Dst + ((size_t)((b * 16 + n) * 64 + i)) * CDIM + joff;
            #pragma unroll
            for (int nt = 0; nt < 7; nt++)
                *reinterpret_cast<half2*>(base + nt * 8) = __floats2half2_rn(
                    acc[mt][nt][rh * 2 + 0] * scale, acc[mt][nt][rh * 2 + 1] * scale);
        }
}

// ---------------- kernel 2: local window attention, fp16 tensor cores + ldmatrix ----------------
__global__ __launch_bounds__(128) void local_attn(const float* __restrict__ pe1)
{
    __shared__ __half sQ[64 * 40];
    __shared__ __half sK[64 * 40];
    __shared__ __half sVT[32 * 72];
    __shared__ __half sP[64 * 72];

    const int tid = threadIdx.x;
    const int wid = tid >> 5, lane = tid & 31;
    const int g = lane >> 2, tig = lane & 3;
    const int m0 = wid * 16;
    const size_t rowbase = (size_t)blockIdx.x * 64 * CDIM;
    const __half hz = __float2half(0.f);

    const int laA = lane & 15;
    const int kaA = (lane >> 4) * 8;
    const int lbB = lane & 7;
    const int kbB = ((lane >> 3) & 1) * 8;
    const int nsB = ((lane >> 4) & 1) * 8;

    for (int i = tid; i < 256; i += 128) {
        int r = i >> 2, c = 28 + (i & 3);
        sQ[r * 40 + c] = hz; sK[r * 40 + c] = hz;
    }
    for (int i = tid; i < 288; i += 128) sVT[28 * 72 + i] = hz;
    __syncthreads();

    for (int h = 0; h < 4; h++) {
        const int ch0 = h * 28;
        #pragma unroll
        for (int p = 0; p < 4; p++) {
            int idx = tid + p * 128;
            if (idx < 448) {
                int rr = idx / 7, c4 = (idx % 7) << 2;
                size_t ga = rowbase + (size_t)rr * CDIM + ch0 + c4;
                *reinterpret_cast<uint2*>(sQ + rr * 40 + c4) =
                    *reinterpret_cast<const uint2*>(g_QH + ga);
                *reinterpret_cast<uint2*>(sK + rr * 40 + c4) =
                    *reinterpret_cast<const uint2*>(g_KH + ga);
                uint2 v = *reinterpret_cast<const uint2*>(g_VH + ga);
                __half2 v01 = *reinterpret_cast<__half2*>(&v.x);
                __half2 v23 = *reinterpret_cast<__half2*>(&v.y);
                sVT[(c4 + 0) * 72 + rr] = __low2half(v01);
                sVT[(c4 + 1) * 72 + rr] = __high2half(v01);
                sVT[(c4 + 2) * 72 + rr] = __low2half(v23);
                sVT[(c4 + 3) * 72 + rr] = __high2half(v23);
            }
        }
        __syncthreads();

        // ---- S = Q K^T : ldmatrix fragments ----
        float accS[8][4];
        #pragma unroll
        for (int nt = 0; nt < 8; nt++)
            #pragma unroll
            for (int e = 0; e < 4; e++) accS[nt][e] = 0.f;
        #pragma unroll
        for (int ks = 0; ks < 2; ks++) {
            const int kb = ks * 16;
            unsigned a[4];
            ldsm4(a[0], a[1], a[2], a[3], sQ + (m0 + laA) * 40 + kb + kaA);
            unsigned bf[8][2];
            #pragma unroll
            for (int ntp = 0; ntp < 4; ntp++)
                ldsm4(bf[2 * ntp][0], bf[2 * ntp][1], bf[2 * ntp + 1][0], bf[2 * ntp + 1][1],
                      sK + (ntp * 16 + nsB + lbB) * 40 + kb + kbB);
            #pragma unroll
            for (int nt = 0; nt < 8; nt++)
                MMA_F16(accS[nt], a[0], a[1], a[2], a[3], bf[nt][0], bf[nt][1]);
        }

        // ---- + pos_emb1, softmax on fragments ----
        const float* pe = pe1 + (size_t)h * 4096;
        #pragma unroll
        for (int nt = 0; nt < 8; nt++) {
            float2 p0 = *reinterpret_cast<const float2*>(pe + (m0 + g) * 64 + nt * 8 + 2 * tig);
            float2 p1 = *reinterpret_cast<const float2*>(pe + (m0 + 8 + g) * 64 + nt * 8 + 2 * tig);
            accS[nt][0] += p0.x; accS[nt][1] += p0.y;
            accS[nt][2] += p1.x; accS[nt][3] += p1.y;
        }
        float m0v = -1e30f, m1v = -1e30f;
        #pragma unroll
        for (int nt = 0; nt < 8; nt++) {
            m0v = fmaxf(m0v, fmaxf(accS[nt][0], accS[nt][1]));
            m1v = fmaxf(m1v, fmaxf(accS[nt][2], accS[nt][3]));
        }
        m0v = fmaxf(m0v, __shfl_xor_sync(0xffffffffu, m0v, 1));
        m0v = fmaxf(m0v, __shfl_xor_sync(0xffffffffu, m0v, 2));
        m1v = fmaxf(m1v, __shfl_xor_sync(0xffffffffu, m1v, 1));
        m1v = fmaxf(m1v, __shfl_xor_sync(0xffffffffu, m1v, 2));
        float s0 = 0.f, s1 = 0.f;
        #pragma unroll
        for (int nt = 0; nt < 8; nt++) {
            accS[nt][0] = __expf(accS[nt][0] - m0v); s0 += accS[nt][0];
            accS[nt][1] = __expf(accS[nt][1] - m0v); s0 += accS[nt][1];
            accS[nt][2] = __expf(accS[nt][2] - m1v); s1 += accS[nt][2];
            accS[nt][3] = __expf(accS[nt][3] - m1v); s1 += accS[nt][3];
        }
        s0 += __shfl_xor_sync(0xffffffffu, s0, 1);
        s0 += __shfl_xor_sync(0xffffffffu, s0, 2);
        s1 += __shfl_xor_sync(0xffffffffu, s1, 1);
        s1 += __shfl_xor_sync(0xffffffffu, s1, 2);
        const float i0 = 1.f / s0, i1 = 1.f / s1;
        #pragma unroll
        for (int nt = 0; nt < 8; nt++) {
            *reinterpret_cast<half2*>(sP + (m0 + g) * 72 + nt * 8 + 2 * tig) =
                __floats2half2_rn(accS[nt][0] * i0, accS[nt][1] * i0);
            *reinterpret_cast<half2*>(sP + (m0 + 8 + g) * 72 + nt * 8 + 2 * tig) =
                __floats2half2_rn(accS[nt][2] * i1, accS[nt][3] * i1);
        }
        __syncwarp();

        // ---- O = P V : ldmatrix fragments ----
        float accO[4][4];
        #pragma unroll
        for (int nt = 0; nt < 4; nt++)
            #pragma unroll
            for (int e = 0; e < 4; e++) accO[nt][e] = 0.f;
        #pragma unroll
        for (int ks = 0; ks < 4; ks++) {
            const int kb = ks * 16;
            unsigned a[4];
            ldsm4(a[0], a[1], a[2], a[3], sP + (m0 + laA) * 72 + kb + kaA);
            unsigned bf[4][2];
            #pragma unroll
            for (int ntp = 0; ntp < 2; ntp++)
                ldsm4(bf[2 * ntp][0], bf[2 * ntp][1], bf[2 * ntp + 1][0], bf[2 * ntp + 1][1],
                      sVT + (ntp * 16 + nsB + lbB) * 72 + kb + kbB);
            #pragma unroll
            for (int nt = 0; nt < 4; nt++)
                MMA_F16(accO[nt], a[0], a[1], a[2], a[3], bf[nt][0], bf[nt][1]);
        }
        __half* row0 = g_AttnH + rowbase + (size_t)(m0 + g) * CDIM;
        __half* row1 = g_AttnH + rowbase + (size_t)(m0 + 8 + g) * CDIM;
        #pragma unroll
        for (int nt = 0; nt < 4; nt++) {
            int col = nt * 8 + 2 * tig;
            if (col < 28) {
                *reinterpret_cast<half2*>(row0 + ch0 + col) =
                    __floats2half2_rn(accO[nt][0], accO[nt][1]);
                *reinterpret_cast<half2*>(row1 + ch0 + col) =
                    __floats2half2_rn(accO[nt][2], accO[nt][3]);
            }
        }
        __syncthreads();
    }
}

// ---------------- kernel 3: global attention (channels 112..223) ----------------
__global__ __launch_bounds__(128) void global_attn(const float* __restrict__ pe2)
{
    __shared__ float qs[16 * 116];
    __shared__ float kTs[112 * 20];
    __shared__ float vs[16 * 116];
    __shared__ float ps[4 * 16 * 17];

    const int tid = threadIdx.x;
    const int b = blockIdx.x >> 6, ipos = blockIdx.x & 63;
    const size_t base0 = ((size_t)(b * 16) * 64 + ipos) * CDIM + 112;

    #pragma unroll
    for (int p = 0; p < 4; p++) {
        int idx = tid + p * 128;
        if (idx < 448) {
            int n = idx / 28, c4 = (idx % 28) << 2;
            size_t ga = base0 + (size_t)n * (64 * CDIM) + c4;
            uint2 qv = *reinterpret_cast<const uint2*>(g_QH + ga);
            uint2 vv = *reinterpret_cast<const uint2*>(g_VH + ga);
            uint2 kv = *reinterpret_cast<const uint2*>(g_KH + ga);
            float2 q01 = __half22float2(*reinterpret_cast<__half2*>(&qv.x));
            float2 q23 = __half22float2(*reinterpret_cast<__half2*>(&qv.y));
            float2 v01 = __half22float2(*reinterpret_cast<__half2*>(&vv.x));
            float2 v23 = __half22float2(*reinterpret_cast<__half2*>(&vv.y));
            float2 k01 = __half22float2(*reinterpret_cast<__half2*>(&kv.x));
            float2 k23 = __half22float2(*reinterpret_cast<__half2*>(&kv.y));
            qs[n * 116 + c4 + 0] = q01.x; qs[n * 116 + c4 + 1] = q01.y;
            qs[n * 116 + c4 + 2] = q23.x; qs[n * 116 + c4 + 3] = q23.y;
            vs[n * 116 + c4 + 0] = v01.x; vs[n * 116 + c4 + 1] = v01.y;
            vs[n * 116 + c4 + 2] = v23.x; vs[n * 116 + c4 + 3] = v23.y;
            kTs[(c4 + 0) * 20 + n] = k01.x; kTs[(c4 + 1) * 20 + n] = k01.y;
            kTs[(c4 + 2) * 20 + n] = k23.x; kTs[(c4 + 3) * 20 + n] = k23.y;
        }
    }
    __syncthreads();

    const int h = tid >> 5, lane = tid & 31;
    const int r = lane >> 1, cb = (lane & 1) << 3;

    float qreg[28];
    #pragma unroll
    for (int u = 0; u < 7; u++) {
        float4 f = *reinterpret_cast<float4*>(qs + r * 116 + h * 28 + 4 * u);
        qreg[4 * u] = f.x; qreg[4 * u + 1] = f.y; qreg[4 * u + 2] = f.z; qreg[4 * u + 3] = f.w;
    }
    float s[8];
    #pragma unroll
    for (int j = 0; j < 8; j++) s[j] = 0.f;
    #pragma unroll
    for (int d = 0; d < 28; d++)
        #pragma unroll
        for (int j = 0; j < 8; j++) s[j] += qreg[d] * kTs[(h * 28 + d) * 20 + cb + j];

    const float* pr = pe2 + (size_t)h * 256 + r * 16 + cb;
    #pragma unroll
    for (int j = 0; j < 8; j++) s[j] += pr[j];
    float m = s[0];
    #pragma unroll
    for (int j = 1; j < 8; j++) m = fmaxf(m, s[j]);
    m = fmaxf(m, __shfl_xor_sync(0xffffffffu, m, 1));
    float sum = 0.f;
    #pragma unroll
    for (int j = 0; j < 8; j++) { s[j] = __expf(s[j] - m); sum += s[j]; }
    sum += __shfl_xor_sync(0xffffffffu, sum, 1);
    const float inv = 1.f / sum;
    #pragma unroll
    for (int j = 0; j < 8; j++) ps[h * 272 + r * 17 + cb + j] = s[j] * inv;
    __syncwarp();

    const int chb = (lane & 1) * 14;
    float accO[14];
    #pragma unroll
    for (int c = 0; c < 14; c++) accO[c] = 0.f;
    #pragma unroll
    for (int j = 0; j < 16; j++) {
        float p = ps[h * 272 + r * 17 + j];
        #pragma unroll
        for (int c = 0; c < 14; c++) accO[c] += p * vs[j * 116 + h * 28 + chb + c];
    }
    __half* od = g_AttnH + ((size_t)((b * 16 + r) * 64 + ipos)) * CDIM + 112 + h * 28 + chb;
    #pragma unroll
    for (int c = 0; c < 14; c++) od[c] = __float2half_rn(accO[c]);
}

// ---------------- kernel 4: out-proj + bias + window-reverse ----------------
__global__ __launch_bounds__(256, 2) void proj_kernel(
    const float* __restrict__ bout, float* __restrict__ out)
{
    extern __shared__ __half smem[];
    float acc[2][7][4] = {};
    const int ctan = blockIdx.x, ctam = blockIdx.y;

    gemm_fp16(g_AttnH + (size_t)ctam * 128 * CDIM,
              g_WoutT + (size_t)(ctan * 112) * CDIM, smem, acc);

    const int tid = threadIdx.x, wid = tid >> 5, lane = tid & 31;
    const int g = lane >> 2, tig = lane & 3, wm = wid >> 1, wn = wid & 1;
    const int joff = ctan * 112 + wn * 56 + tig * 2;

    #pragma unroll
    for (int mt = 0; mt < 2; mt++)
        #pragma unroll
        for (int rh = 0; rh < 2; rh++) {
            int r = wm * 32 + mt * 16 + rh * 8 + g;
            int t = ctam * 128 + r;
            int b = t >> 10, n = (t >> 6) & 15, i = t & 63;
            int hr = (n >> 2) * 8 + (i >> 3), wc = (n & 3) * 8 + (i & 7);
            float* base = out + ((size_t)((b * 32 + hr) * 32 + wc)) * CDIM + joff;
            #pragma unroll
            for (int nt = 0; nt < 7; nt++) {
                float2 bo = *reinterpret_cast<const float2*>(bout + joff + nt * 8);
                *reinterpret_cast<float2*>(base + nt * 8) =
                    make_float2(acc[mt][nt][rh * 2 + 0] + bo.x, acc[mt][nt][rh * 2 + 1] + bo.y);
            }
        }
}

extern "C" void kernel_launch(void* const* d_in, const int* in_sizes, int n_in,
                              void* d_out, int out_size) {
    const float* x    = (const float*)d_in[0];
    const float* Wq   = (const float*)d_in[1];
    const float* Wkv  = (const float*)d_in[2];
    const float* Wout = (const float*)d_in[3];
    const float* bout = (const float*)d_in[4];
    const float* pe1  = (const float*)d_in[5];
    const float* pe2  = (const float*)d_in[6];
    float* out = (float*)d_out;

    cudaFuncSetAttribute(qkv_kernel,  cudaFuncAttributeMaxDynamicSharedMemorySize, GEMM_SMEM_BYTES);
    cudaFuncSetAttribute(proj_kernel, cudaFuncAttributeMaxDynamicSharedMemorySize, GEMM_SMEM_BYTES);

    __half* gX;     cudaGetSymbolAddress((void**)&gX,     g_X);
    __half* gWqT;   cudaGetSymbolAddress((void**)&gWqT,   g_WqT);
    __half* gWkvT;  cudaGetSymbolAddress((void**)&gWkvT,  g_WkvT);
    __half* gWoutT; cudaGetSymbolAddress((void**)&gWoutT, g_WoutT);

    conv_x<<<28672, 256>>>(x, gX, 29360128 / 4);
    transp_conv_all<<<dim3(28, 7), dim3(32, 32)>>>(Wq, Wkv, Wout, gWqT, gWkvT, gWoutT);

    qkv_kernel<<<dim3(6, 1024), 256, GEMM_SMEM_BYTES>>>();
    local_attn<<<2048, 128>>>(pe1);
    global_attn<<<8192, 128>>>(pe2);
    proj_kernel<<<dim3(2, 1024), 256, GEMM_SMEM_BYTES>>>(bout, out);
}

// round 17
// speedup vs baseline: 1.0854x; 1.0071x over previous
#include <cuda_runtime.h>
#include <cuda_fp16.h>
#include <cstdint>
#include <cstddef>

#define CDIM 224
#define SCALE_Q 0.18898223650461363f
#define STAGE_H 9600              // 128*40 (A) + 112*40 (B) halves
#define NSTAGE 3
#define GEMM_SMEM_BYTES (NSTAGE * STAGE_H * 2)

__device__ __half g_QH[29360128];
__device__ __half g_KH[29360128];
__device__ __half g_VH[29360128];
__device__ __half g_AttnH[29360128];
__device__ __half g_X[29360128];
__device__ __half g_WqT[50176];
__device__ __half g_WkvT[100352];
__device__ __half g_WoutT[50176];

__device__ __forceinline__ void cp16h(__half* smem_dst, const __half* gsrc) {
    unsigned s = (unsigned)__cvta_generic_to_shared(smem_dst);
    asm volatile("cp.async.cg.shared.global [%0], [%1], 16;" :: "r"(s), "l"(gsrc) : "memory");
}
__device__ __forceinline__ void ldsm4(unsigned& r0, unsigned& r1, unsigned& r2, unsigned& r3,
                                      const __half* p) {
    uint32_t a = (uint32_t)__cvta_generic_to_shared(p);
    asm volatile("ldmatrix.sync.aligned.m8n8.x4.shared.b16 {%0,%1,%2,%3}, [%4];"
                 : "=r"(r0), "=r"(r1), "=r"(r2), "=r"(r3) : "r"(a));
}
__device__ __forceinline__ void ldsm4t(unsigned& r0, unsigned& r1, unsigned& r2, unsigned& r3,
                                       const __half* p) {
    uint32_t a = (uint32_t)__cvta_generic_to_shared(p);
    asm volatile("ldmatrix.sync.aligned.m8n8.x4.trans.shared.b16 {%0,%1,%2,%3}, [%4];"
                 : "=r"(r0), "=r"(r1), "=r"(r2), "=r"(r3) : "r"(a));
}
__device__ __forceinline__ void ldsm2(unsigned& r0, unsigned& r1, const __half* p) {
    uint32_t a = (uint32_t)__cvta_generic_to_shared(p);
    asm volatile("ldmatrix.sync.aligned.m8n8.x2.shared.b16 {%0,%1}, [%2];"
                 : "=r"(r0), "=r"(r1) : "r"(a));
}
#define MMA_F16(acc, a0,a1,a2,a3, b0,b1) \
    asm volatile("mma.sync.aligned.m16n8k16.row.col.f32.f16.f16.f32 " \
        "{%0,%1,%2,%3}, {%4,%5,%6,%7}, {%8,%9}, {%0,%1,%2,%3};\n" \
        : "+f"(acc[0]), "+f"(acc[1]), "+f"(acc[2]), "+f"(acc[3]) \
        : "r"(a0), "r"(a1), "r"(a2), "r"(a3), "r"(b0), "r"(b1))

// ---------------- prepasses ----------------
__global__ __launch_bounds__(256) void conv_x(
    const float* __restrict__ src, __half* __restrict__ dst, int n4)
{
    int i = blockIdx.x * blockDim.x + threadIdx.x;
    if (i < n4) {
        float4 f = reinterpret_cast<const float4*>(src)[i];
        half2 h0 = __floats2half2_rn(f.x, f.y);
        half2 h1 = __floats2half2_rn(f.z, f.w);
        *reinterpret_cast<uint2*>(dst + 4 * (size_t)i) =
            make_uint2(*reinterpret_cast<unsigned*>(&h0), *reinterpret_cast<unsigned*>(&h1));
    }
}
__global__ __launch_bounds__(1024) void transp_conv_all(
    const float* __restrict__ Wq, const float* __restrict__ Wkv, const float* __restrict__ Wout,
    __half* __restrict__ WqT, __half* __restrict__ WkvT, __half* __restrict__ WoutT)
{
    __shared__ float t[32][33];
    int bx = blockIdx.x;
    const float* W; __half* WT; int N, nb;
    if (bx < 7)       { W = Wq;   WT = WqT;   N = 224; nb = bx; }
    else if (bx < 21) { W = Wkv;  WT = WkvT;  N = 448; nb = bx - 7; }
    else              { W = Wout; WT = WoutT; N = 224; nb = bx - 21; }
    int n0 = nb * 32, k0 = blockIdx.y * 32;
    t[threadIdx.y][threadIdx.x] = W[(size_t)(k0 + threadIdx.y) * N + n0 + threadIdx.x];
    __syncthreads();
    WT[(size_t)(n0 + threadIdx.y) * 224 + k0 + threadIdx.x] =
        __float2half_rn(t[threadIdx.x][threadIdx.y]);
}

// ---------------- fp16 3-stage pipelined GEMM + ldmatrix: BM=128 BN=112 BK=32 ----------------
__device__ __forceinline__ void gemm_fp16(
    const __half* __restrict__ A, const __half* __restrict__ BT,
    __half* smem, float (&acc)[2][7][4])
{
    const int tid = threadIdx.x;
    const int wid = tid >> 5, lane = tid & 31;
    const int wm = wid >> 1, wn = wid & 1;

    const int laA  = lane & 15;
    const int kaA  = (lane >> 4) * 8;
    const int lbB  = lane & 7;
    const int kbB  = ((lane >> 3) & 1) * 8;
    const int nsB  = ((lane >> 4) & 1) * 8;

    auto issue = [&](int kt, int stage) {
        __half* sA = smem + stage * STAGE_H;
        __half* sB = sA + 5120;
        #pragma unroll
        for (int p = 0; p < 2; p++) {
            int q = tid + p * 256;
            int r = q >> 2, c8 = (q & 3) * 8;
            cp16h(sA + r * 40 + c8, A + (size_t)r * CDIM + kt + c8);
        }
        #pragma unroll
        for (int p = 0; p < 2; p++) {
            int q = tid + p * 256;
            if (q < 448) {
                int n = q >> 2, c8 = (q & 3) * 8;
                cp16h(sB + n * 40 + c8, BT + (size_t)n * CDIM + kt + c8);
            }
        }
        asm volatile("cp.async.commit_group;" ::: "memory");
    };

    issue(0, 0);
    issue(32, 1);
    #pragma unroll
    for (int it = 0; it < 7; it++) {
        if (it == 6) asm volatile("cp.async.wait_group 0;" ::: "memory");
        else         asm volatile("cp.async.wait_group 1;" ::: "memory");
        __syncthreads();
        __half* sA = smem + (it % NSTAGE) * STAGE_H;
        __half* sB = sA + 5120;
        #pragma unroll
        for (int ks = 0; ks < 2; ks++) {
            const int kb = ks * 16;
            unsigned af[2][4];
            #pragma unroll
            for (int mt = 0; mt < 2; mt++)
                ldsm4(af[mt][0], af[mt][1], af[mt][2], af[mt][3],
                      sA + (wm * 32 + mt * 16 + laA) * 40 + kb + kaA);
            unsigned bf[7][2];
            #pragma unroll
            for (int ntp = 0; ntp < 3; ntp++)
                ldsm4(bf[2 * ntp][0], bf[2 * ntp][1], bf[2 * ntp + 1][0], bf[2 * ntp + 1][1],
                      sB + (wn * 56 + ntp * 16 + nsB + lbB) * 40 + kb + kbB);
            ldsm2(bf[6][0], bf[6][1], sB + (wn * 56 + 48 + lbB) * 40 + kb + kbB);
            #pragma unroll
            for (int mt = 0; mt < 2; mt++)
                #pragma unroll
                for (int nt = 0; nt < 7; nt++)
                    MMA_F16(acc[mt][nt], af[mt][0], af[mt][1], af[mt][2], af[mt][3],
                            bf[nt][0], bf[nt][1]);
        }
        if (it + 2 < 7) issue((it + 2) * 32, (it + 2) % NSTAGE);
    }
}

// ---------------- kernel 1: QKV + window-partition permute + q*SCALE (fp16 out) ----------------
__global__ __launch_bounds__(256, 2) void qkv_kernel()
{
    extern __shared__ __half smem[];
    float acc[2][7][4] = {};
    const int ctan = blockIdx.x, ctam = blockIdx.y;

    const __half* BT;
    if (ctan < 2) BT = g_WqT  + (size_t)(ctan * 112) * CDIM;
    else          BT = g_WkvT + (size_t)((ctan - 2) * 112) * CDIM;

    gemm_fp16(g_X + (size_t)ctam * 128 * CDIM, BT, smem, acc);

    __half* Dst = (ctan < 2) ? g_QH : (ctan < 4 ? g_KH : g_VH);
    const float scale = (ctan < 2) ? SCALE_Q : 1.0f;
    const int tid = threadIdx.x, wid = tid >> 5, lane = tid & 31;
    const int g = lane >> 2, tig = lane & 3, wm = wid >> 1, wn = wid & 1;
    const int joff = (ctan & 1) * 112 + wn * 56 + tig * 2;

    #pragma unroll
    for (int mt = 0; mt < 2; mt++)
        #pragma unroll
        for (int rh = 0; rh < 2; rh++) {
            int r = wm * 32 + mt * 16 + rh * 8 + g;
            int t = ctam * 128 + r;
            int b = t >> 10, hr = (t >> 5) & 31, wc = t & 31;
            int n = ((hr >> 3) << 2) + (wc >> 3);
            int i = ((hr & 7) << 3) + (wc & 7);
            __half* base = Dst + ((size_t)((b * 16 + n) * 64 + i)) * CDIM + joff;
            #pragma unroll
            for (int nt = 0; nt < 7; nt++)
                *reinterpret_cast<half2*>(base + nt * 8) = __floats2half2_rn(
                    acc[mt][nt][rh * 2 + 0] * scale, acc[mt][nt][rh * 2 + 1] * scale);
        }
}

// ---------------- kernel 2: local window attention, fp16 TC + ldmatrix(.trans) ----------------
__global__ __launch_bounds__(128) void local_attn(const float* __restrict__ pe1)
{
    __shared__ __half sQ[64 * 40];
    __shared__ __half sK[64 * 40];
    __shared__ __half sV[64 * 40];    // natural [key][channel]
    __shared__ __half sP[64 * 72];

    const int tid = threadIdx.x;
    const int wid = tid >> 5, lane = tid & 31;
    const int g = lane >> 2, tig = lane & 3;
    const int m0 = wid * 16;
    const size_t rowbase = (size_t)blockIdx.x * 64 * CDIM;
    const __half hz = __float2half(0.f);

    const int laA = lane & 15;
    const int kaA = (lane >> 4) * 8;
    const int lbB = lane & 7;
    const int kbB = ((lane >> 3) & 1) * 8;
    const int nsB = ((lane >> 4) & 1) * 8;

    for (int i = tid; i < 256; i += 128) {
        int r = i >> 2, c = 28 + (i & 3);
        sQ[r * 40 + c] = hz; sK[r * 40 + c] = hz; sV[r * 40 + c] = hz;
    }
    __syncthreads();

    for (int h = 0; h < 4; h++) {
        const int ch0 = h * 28;
        #pragma unroll
        for (int p = 0; p < 4; p++) {
            int idx = tid + p * 128;
            if (idx < 448) {
                int rr = idx / 7, c4 = (idx % 7) << 2;
                size_t ga = rowbase + (size_t)rr * CDIM + ch0 + c4;
                *reinterpret_cast<uint2*>(sQ + rr * 40 + c4) =
                    *reinterpret_cast<const uint2*>(g_QH + ga);
                *reinterpret_cast<uint2*>(sK + rr * 40 + c4) =
                    *reinterpret_cast<const uint2*>(g_KH + ga);
                *reinterpret_cast<uint2*>(sV + rr * 40 + c4) =
                    *reinterpret_cast<const uint2*>(g_VH + ga);
            }
        }
        __syncthreads();

        // ---- S = Q K^T : ldmatrix fragments ----
        float accS[8][4];
        #pragma unroll
        for (int nt = 0; nt < 8; nt++)
            #pragma unroll
            for (int e = 0; e < 4; e++) accS[nt][e] = 0.f;
        #pragma unroll
        for (int ks = 0; ks < 2; ks++) {
            const int kb = ks * 16;
            unsigned a[4];
            ldsm4(a[0], a[1], a[2], a[3], sQ + (m0 + laA) * 40 + kb + kaA);
            unsigned bf[8][2];
            #pragma unroll
            for (int ntp = 0; ntp < 4; ntp++)
                ldsm4(bf[2 * ntp][0], bf[2 * ntp][1], bf[2 * ntp + 1][0], bf[2 * ntp + 1][1],
                      sK + (ntp * 16 + nsB + lbB) * 40 + kb + kbB);
            #pragma unroll
            for (int nt = 0; nt < 8; nt++)
                MMA_F16(accS[nt], a[0], a[1], a[2], a[3], bf[nt][0], bf[nt][1]);
        }

        // ---- + pos_emb1, softmax on fragments ----
        const float* pe = pe1 + (size_t)h * 4096;
        #pragma unroll
        for (int nt = 0; nt < 8; nt++) {
            float2 p0 = *reinterpret_cast<const float2*>(pe + (m0 + g) * 64 + nt * 8 + 2 * tig);
            float2 p1 = *reinterpret_cast<const float2*>(pe + (m0 + 8 + g) * 64 + nt * 8 + 2 * tig);
            accS[nt][0] += p0.x; accS[nt][1] += p0.y;
            accS[nt][2] += p1.x; accS[nt][3] += p1.y;
        }
        float m0v = -1e30f, m1v = -1e30f;
        #pragma unroll
        for (int nt = 0; nt < 8; nt++) {
            m0v = fmaxf(m0v, fmaxf(accS[nt][0], accS[nt][1]));
            m1v = fmaxf(m1v, fmaxf(accS[nt][2], accS[nt][3]));
        }
        m0v = fmaxf(m0v, __shfl_xor_sync(0xffffffffu, m0v, 1));
        m0v = fmaxf(m0v, __shfl_xor_sync(0xffffffffu, m0v, 2));
        m1v = fmaxf(m1v, __shfl_xor_sync(0xffffffffu, m1v, 1));
        m1v = fmaxf(m1v, __shfl_xor_sync(0xffffffffu, m1v, 2));
        float s0 = 0.f, s1 = 0.f;
        #pragma unroll
        for (int nt = 0; nt < 8; nt++) {
            accS[nt][0] = __expf(accS[nt][0] - m0v); s0 += accS[nt][0];
            accS[nt][1] = __expf(accS[nt][1] - m0v); s0 += accS[nt][1];
            accS[nt][2] = __expf(accS[nt][2] - m1v); s1 += accS[nt][2];
            accS[nt][3] = __expf(accS[nt][3] - m1v); s1 += accS[nt][3];
        }
        s0 += __shfl_xor_sync(0xffffffffu, s0, 1);
        s0 += __shfl_xor_sync(0xffffffffu, s0, 2);
        s1 += __shfl_xor_sync(0xffffffffu, s1, 1);
        s1 += __shfl_xor_sync(0xffffffffu, s1, 2);
        const float i0 = 1.f / s0, i1 = 1.f / s1;
        #pragma unroll
        for (int nt = 0; nt < 8; nt++) {
            *reinterpret_cast<half2*>(sP + (m0 + g) * 72 + nt * 8 + 2 * tig) =
                __floats2half2_rn(accS[nt][0] * i0, accS[nt][1] * i0);
            *reinterpret_cast<half2*>(sP + (m0 + 8 + g) * 72 + nt * 8 + 2 * tig) =
                __floats2half2_rn(accS[nt][2] * i1, accS[nt][3] * i1);
        }
        __syncwarp();

        // ---- O = P V : A via ldmatrix, B via ldmatrix.trans on natural V ----
        float accO[4][4];
        #pragma unroll
        for (int nt = 0; nt < 4; nt++)
            #pragma unroll
            for (int e = 0; e < 4; e++) accO[nt][e] = 0.f;
        #pragma unroll
        for (int ks = 0; ks < 4; ks++) {
            const int kb = ks * 16;
            unsigned a[4];
            ldsm4(a[0], a[1], a[2], a[3], sP + (m0 + laA) * 72 + kb + kaA);
            unsigned bf[4][2];
            #pragma unroll
            for (int ntp = 0; ntp < 2; ntp++)
                ldsm4t(bf[2 * ntp][0], bf[2 * ntp][1], bf[2 * ntp + 1][0], bf[2 * ntp + 1][1],
                       sV + (kb + kbB + lbB) * 40 + ntp * 16 + nsB);
            #pragma unroll
            for (int nt = 0; nt < 4; nt++)
                MMA_F16(accO[nt], a[0], a[1], a[2], a[3], bf[nt][0], bf[nt][1]);
        }
        __half* row0 = g_AttnH + rowbase + (size_t)(m0 + g) * CDIM;
        __half* row1 = g_AttnH + rowbase + (size_t)(m0 + 8 + g) * CDIM;
        #pragma unroll
        for (int nt = 0; nt < 4; nt++) {
            int col = nt * 8 + 2 * tig;
            if (col < 28) {
                *reinterpret_cast<half2*>(row0 + ch0 + col) =
                    __floats2half2_rn(accO[nt][0], accO[nt][1]);
                *reinterpret_cast<half2*>(row1 + ch0 + col) =
                    __floats2half2_rn(accO[nt][2], accO[nt][3]);
            }
        }
        __syncthreads();
    }
}

// ---------------- kernel 3: global attention (channels 112..223) ----------------
__global__ __launch_bounds__(128) void global_attn(const float* __restrict__ pe2)
{
    __shared__ float qs[16 * 116];
    __shared__ float kTs[112 * 20];
    __shared__ float vs[16 * 116];
    __shared__ float ps[4 * 16 * 17];

    const int tid = threadIdx.x;
    const int b = blockIdx.x >> 6, ipos = blockIdx.x & 63;
    const size_t base0 = ((size_t)(b * 16) * 64 + ipos) * CDIM + 112;

    #pragma unroll
    for (int p = 0; p < 4; p++) {
        int idx = tid + p * 128;
        if (idx < 448) {
            int n = idx / 28, c4 = (idx % 28) << 2;
            size_t ga = base0 + (size_t)n * (64 * CDIM) + c4;
            uint2 qv = *reinterpret_cast<const uint2*>(g_QH + ga);
            uint2 vv = *reinterpret_cast<const uint2*>(g_VH + ga);
            uint2 kv = *reinterpret_cast<const uint2*>(g_KH + ga);
            float2 q01 = __half22float2(*reinterpret_cast<__half2*>(&qv.x));
            float2 q23 = __half22float2(*reinterpret_cast<__half2*>(&qv.y));
            float2 v01 = __half22float2(*reinterpret_cast<__half2*>(&vv.x));
            float2 v23 = __half22float2(*reinterpret_cast<__half2*>(&vv.y));
            float2 k01 = __half22float2(*reinterpret_cast<__half2*>(&kv.x));
            float2 k23 = __half22float2(*reinterpret_cast<__half2*>(&kv.y));
            qs[n * 116 + c4 + 0] = q01.x; qs[n * 116 + c4 + 1] = q01.y;
            qs[n * 116 + c4 + 2] = q23.x; qs[n * 116 + c4 + 3] = q23.y;
            vs[n * 116 + c4 + 0] = v01.x; vs[n * 116 + c4 + 1] = v01.y;
            vs[n * 116 + c4 + 2] = v23.x; vs[n * 116 + c4 + 3] = v23.y;
            kTs[(c4 + 0) * 20 + n] = k01.x; kTs[(c4 + 1) * 20 + n] = k01.y;
            kTs[(c4 + 2) * 20 + n] = k23.x; kTs[(c4 + 3) * 20 + n] = k23.y;
        }
    }
    __syncthreads();

    const int h = tid >> 5, lane = tid & 31;
    const int r = lane >> 1, cb = (lane & 1) << 3;

    float qreg[28];
    #pragma unroll
    for (int u = 0; u < 7; u++) {
        float4 f = *reinterpret_cast<float4*>(qs + r * 116 + h * 28 + 4 * u);
        qreg[4 * u] = f.x; qreg[4 * u + 1] = f.y; qreg[4 * u + 2] = f.z; qreg[4 * u + 3] = f.w;
    }
    float s[8];
    #pragma unroll
    for (int j = 0; j < 8; j++) s[j] = 0.f;
    #pragma unroll
    for (int d = 0; d < 28; d++)
        #pragma unroll
        for (int j = 0; j < 8; j++) s[j] += qreg[d] * kTs[(h * 28 + d) * 20 + cb + j];

    const float* pr = pe2 + (size_t)h * 256 + r * 16 + cb;
    #pragma unroll
    for (int j = 0; j < 8; j++) s[j] += pr[j];
    float m = s[0];
    #pragma unroll
    for (int j = 1; j < 8; j++) m = fmaxf(m, s[j]);
    m = fmaxf(m, __shfl_xor_sync(0xffffffffu, m, 1));
    float sum = 0.f;
    #pragma unroll
    for (int j = 0; j < 8; j++) { s[j] = __expf(s[j] - m); sum += s[j]; }
    sum += __shfl_xor_sync(0xffffffffu, sum, 1);
    const float inv = 1.f / sum;
    #pragma unroll
    for (int j = 0; j < 8; j++) ps[h * 272 + r * 17 + cb + j] = s[j] * inv;
    __syncwarp();

    const int chb = (lane & 1) * 14;
    float accO[14];
    #pragma unroll
    for (int c = 0; c < 14; c++) accO[c] = 0.f;
    #pragma unroll
    for (int j = 0; j < 16; j++) {
        float p = ps[h * 272 + r * 17 + j];
        #pragma unroll
        for (int c = 0; c < 14; c++) accO[c] += p * vs[j * 116 + h * 28 + chb + c];
    }
    __half* od = g_AttnH + ((size_t)((b * 16 + r) * 64 + ipos)) * CDIM + 112 + h * 28 + chb;
    #pragma unroll
    for (int c = 0; c < 14; c++) od[c] = __float2half_rn(accO[c]);
}

// ---------------- kernel 4: out-proj + bias + window-reverse ----------------
__global__ __launch_bounds__(256, 2) void proj_kernel(
    const float* __restrict__ bout, float* __restrict__ out)
{
    extern __shared__ __half smem[];
    float acc[2][7][4] = {};
    const int ctan = blockIdx.x, ctam = blockIdx.y;

    gemm_fp16(g_AttnH + (size_t)ctam * 128 * CDIM,
              g_WoutT + (size_t)(ctan * 112) * CDIM, smem, acc);

    const int tid = threadIdx.x, wid = tid >> 5, lane = tid & 31;
    const int g = lane >> 2, tig = lane & 3, wm = wid >> 1, wn = wid & 1;
    const int joff = ctan * 112 + wn * 56 + tig * 2;

    #pragma unroll
    for (int mt = 0; mt < 2; mt++)
        #pragma unroll
        for (int rh = 0; rh < 2; rh++) {
            int r = wm * 32 + mt * 16 + rh * 8 + g;
            int t = ctam * 128 + r;
            int b = t >> 10, n = (t >> 6) & 15, i = t & 63;
            int hr = (n >> 2) * 8 + (i >> 3), wc = (n & 3) * 8 + (i & 7);
            float* base = out + ((size_t)((b * 32 + hr) * 32 + wc)) * CDIM + joff;
            #pragma unroll
            for (int nt = 0; nt < 7; nt++) {
                float2 bo = *reinterpret_cast<const float2*>(bout + joff + nt * 8);
                *reinterpret_cast<float2*>(base + nt * 8) =
                    make_float2(acc[mt][nt][rh * 2 + 0] + bo.x, acc[mt][nt][rh * 2 + 1] + bo.y);
            }
        }
}

extern "C" void kernel_launch(void* const* d_in, const int* in_sizes, int n_in,
                              void* d_out, int out_size) {
    const float* x    = (const float*)d_in[0];
    const float* Wq   = (const float*)d_in[1];
    const float* Wkv  = (const float*)d_in[2];
    const float* Wout = (const float*)d_in[3];
    const float* bout = (const float*)d_in[4];
    const float* pe1  = (const float*)d_in[5];
    const float* pe2  = (const float*)d_in[6];
    float* out = (float*)d_out;

    cudaFuncSetAttribute(qkv_kernel,  cudaFuncAttributeMaxDynamicSharedMemorySize, GEMM_SMEM_BYTES);
    cudaFuncSetAttribute(proj_kernel, cudaFuncAttributeMaxDynamicSharedMemorySize, GEMM_SMEM_BYTES);

    __half* gX;     cudaGetSymbolAddress((void**)&gX,     g_X);
    __half* gWqT;   cudaGetSymbolAddress((void**)&gWqT,   g_WqT);
    __half* gWkvT;  cudaGetSymbolAddress((void**)&gWkvT,  g_WkvT);
    __half* gWoutT; cudaGetSymbolAddress((void**)&gWoutT, g_WoutT);

    conv_x<<<28672, 256>>>(x, gX, 29360128 / 4);
    transp_conv_all<<<dim3(28, 7), dim3(32, 32)>>>(Wq, Wkv, Wout, gWqT, gWkvT, gWoutT);

    qkv_kernel<<<dim3(6, 1024), 256, GEMM_SMEM_BYTES>>>();
    local_attn<<<2048, 128>>>(pe1);
    global_attn<<<8192, 128>>>(pe2);
    proj_kernel<<<dim3(2, 1024), 256, GEMM_SMEM_BYTES>>>(bout, out);
}